// round 6
// baseline (speedup 1.0000x reference)
#include <cuda_runtime.h>
#include <cuda_fp16.h>

// Problem constants (fixed by the dataset)
#define NN 100000
#define EE 1600000
#define D  64
#define BN_EPS 1e-5f
#define NCH 98   // ceil(NN / 1024)

// ---------------- scratch (static device globals; no allocation) ----------------
__device__ int   g_deg[NN];
__device__ float g_dis[NN];
__device__ int   g_rowptr[NN + 1];
__device__ int   g_fill[NN];
__device__ int   g_psum[128];                             // lookback aggregates (bit31 = ready)
__device__ __align__(16) int2    g_cw[EE];                // packed (col, wgt bits)
__device__ __align__(16) __half2 g_h[(size_t)NN * (D/2)]; // GEMM outputs in fp16 (gather source)
__device__ __align__(16) float   g_buf2[(size_t)NN * D];  // aggregation outputs (fp32)
__device__ float g_bnsum[4 * D];  // [sum1 | sq1 | sum2 | sq2]

// ---------------- kernels ----------------

// Reset per-call state: deg=1 (self loop), psum flags, bn accumulators.
__global__ void k_init() {
    int stride = gridDim.x * blockDim.x;
    for (int i = blockIdx.x * blockDim.x + threadIdx.x; i < NN; i += stride)
        g_deg[i] = 1;
    if (blockIdx.x == 0 && threadIdx.x < 4 * D) g_bnsum[threadIdx.x] = 0.0f;
    if (blockIdx.x == 0 && threadIdx.x < 128)   g_psum[threadIdx.x]  = 0;
    if (blockIdx.x == 0 && threadIdx.x == 0)    g_rowptr[NN] = EE;
}

// In-degree histogram over dst (int4 vectorized; EE % 4 == 0).
__global__ void k_count(const int4* __restrict__ dst4) {
    int stride = gridDim.x * blockDim.x;
    for (int e = blockIdx.x * blockDim.x + threadIdx.x; e < EE / 4; e += stride) {
        int4 d = __ldg(&dst4[e]);
        atomicAdd(&g_deg[d.x], 1);
        atomicAdd(&g_deg[d.y], 1);
        atomicAdd(&g_deg[d.z], 1);
        atomicAdd(&g_deg[d.w], 1);
    }
}

// Single-pass scan with decoupled lookback (98 blocks, all resident -> safe).
// Produces: g_dis = rsqrt(deg), g_rowptr exclusive scan of (deg-1), g_fill = 0.
__global__ void k_scan() {
    __shared__ int s[1024];
    __shared__ int s_off[128];
    int t = threadIdx.x, b = blockIdx.x;
    int idx = b * 1024 + t;
    int d = 0;
    if (idx < NN) {
        int dg = g_deg[idx];
        g_dis[idx]  = rsqrtf((float)dg);
        g_fill[idx] = 0;
        d = dg - 1;  // edge count only (self loop handled separately)
    }
    s[t] = d;
    __syncthreads();
    // Inclusive Hillis-Steele scan within the block.
    #pragma unroll
    for (int off = 1; off < 1024; off <<= 1) {
        int v = (t >= off) ? s[t - off] : 0;
        __syncthreads();
        s[t] += v;
        __syncthreads();
    }
    // Publish aggregate (payload inside the word; bit31 = ready flag).
    if (t == 0) atomicExch(&g_psum[b], s[1023] | 0x80000000);
    // Poll all predecessor aggregates in parallel (one per thread).
    int part = 0;
    if (t < b) {
        int v;
        do { v = *(volatile int*)&g_psum[t]; } while (!(v & 0x80000000));
        part = v & 0x7fffffff;
    }
    if (t < 128) s_off[t] = part;
    __syncthreads();
    #pragma unroll
    for (int o = 64; o > 0; o >>= 1) {
        if (t < o) s_off[t] += s_off[t + o];
        __syncthreads();
    }
    if (idx < NN) g_rowptr[idx] = s_off[0] + s[t] - d;  // exclusive
}

// Scatter edges into CSR buckets; pack (src, dis[src]*dis[dst]) into 8B.
__global__ void k_scatter(const int4* __restrict__ src4, const int4* __restrict__ dst4) {
    int stride = gridDim.x * blockDim.x;
    for (int e = blockIdx.x * blockDim.x + threadIdx.x; e < EE / 4; e += stride) {
        int4 sv = __ldg(&src4[e]);
        int4 dv = __ldg(&dst4[e]);
        int ss[4] = {sv.x, sv.y, sv.z, sv.w};
        int dd[4] = {dv.x, dv.y, dv.z, dv.w};
        #pragma unroll
        for (int j = 0; j < 4; j++) {
            int s = ss[j], d = dd[j];
            int p = atomicAdd(&g_fill[d], 1);
            int o = g_rowptr[d] + p;
            g_cw[o] = make_int2(s, __float_as_int(g_dis[s] * g_dis[d]));
        }
    }
}

// GEMM: g_h (fp16) = X @ W.  mode 0: X = x_ext.  mode 1: X = g_buf2 with fused
// BatchNorm(stats g_bnsum[0..127]) + ReLU on the input read.
// One warp per row (grid-stride); lane owns 2 output cols; W in shared.
__global__ void k_gemm(const float* __restrict__ X_ext,
                       const float* __restrict__ W,
                       const float* __restrict__ gamma,
                       const float* __restrict__ beta,
                       int mode) {
    __shared__ __align__(16) float ws[D * D];
    __shared__ float s_sc[D], s_sh[D];
    int t = threadIdx.x;
    for (int i = t; i < D * D / 4; i += blockDim.x)
        ((float4*)ws)[i] = ((const float4*)W)[i];
    if (mode == 1 && t < D) {
        float inv_n = 1.0f / (float)NN;
        float mu  = g_bnsum[t] * inv_n;
        float var = g_bnsum[D + t] * inv_n - mu * mu;
        float sc  = gamma[t] * rsqrtf(var + BN_EPS);
        s_sc[t] = sc;
        s_sh[t] = beta[t] - mu * sc;
    }
    __syncthreads();

    int warp = t >> 5, lane = t & 31;
    int wpb = blockDim.x >> 5;
    int stride = gridDim.x * wpb;
    const float* X = (mode == 0) ? X_ext : g_buf2;
    for (int row = blockIdx.x * wpb + warp; row < NN; row += stride) {
        float2 xr = ((const float2*)(X + (size_t)row * D))[lane];
        if (mode == 1) {
            xr.x = fmaxf(fmaf(xr.x, s_sc[2 * lane],     s_sh[2 * lane]),     0.0f);
            xr.y = fmaxf(fmaf(xr.y, s_sc[2 * lane + 1], s_sh[2 * lane + 1]), 0.0f);
        }
        float2 acc = make_float2(0.0f, 0.0f);
        #pragma unroll
        for (int k = 0; k < D; k++) {
            float xv = __shfl_sync(0xffffffffu, (k & 1) ? xr.y : xr.x, k >> 1);
            float2 wv = ((const float2*)(ws + k * D))[lane];
            acc.x = fmaf(xv, wv.x, acc.x);
            acc.y = fmaf(xv, wv.y, acc.y);
        }
        g_h[(size_t)row * 32 + lane] = __floats2half2_rn(acc.x, acc.y);
    }
}

// Pull aggregation (fp16 gather source, fp32 accumulate) with FUSED BN stats:
//   g_buf2[n] = bias + dis[n]^2 * h[n] + sum_e w[e]*h[col[e]]
// One warp per node (grid-stride), lane owns 2 features, no float atomics in
// the hot loop. Per-feature sum/sumsq reduced per block, one atomic per feature.
// Requires blockDim == 256.
__global__ void k_agg(const float* __restrict__ bias, int off) {
    __shared__ float ssum[8 * D], ssq[8 * D];
    int t = threadIdx.x;
    int warp = t >> 5, lane = t & 31;
    int stride = gridDim.x * 8;
    const __half2* __restrict__ Hh = g_h;
    float2 b = ((const float2*)bias)[lane];
    float2 ts = make_float2(0.0f, 0.0f);
    float2 tq = make_float2(0.0f, 0.0f);
    for (int n = blockIdx.x * 8 + warp; n < NN; n += stride) {
        float dn = g_dis[n];
        float w0 = dn * dn;
        float2 hv = __half22float2(Hh[(size_t)n * 32 + lane]);
        float2 acc = make_float2(fmaf(w0, hv.x, b.x), fmaf(w0, hv.y, b.y));
        int s0 = g_rowptr[n], e0 = g_rowptr[n + 1];
        #pragma unroll 8
        for (int i = s0; i < e0; i++) {
            int2  cw = __ldg(&g_cw[i]);
            float w  = __int_as_float(cw.y);
            float2 v = __half22float2(__ldg(&Hh[(size_t)cw.x * 32 + lane]));
            acc.x = fmaf(w, v.x, acc.x);
            acc.y = fmaf(w, v.y, acc.y);
        }
        ((float2*)(g_buf2 + (size_t)n * D))[lane] = acc;
        ts.x += acc.x;
        ts.y += acc.y;
        tq.x = fmaf(acc.x, acc.x, tq.x);
        tq.y = fmaf(acc.y, acc.y, tq.y);
    }
    ssum[warp * D + 2 * lane]     = ts.x;
    ssum[warp * D + 2 * lane + 1] = ts.y;
    ssq [warp * D + 2 * lane]     = tq.x;
    ssq [warp * D + 2 * lane + 1] = tq.y;
    __syncthreads();
    if (t < D) {
        float s = 0.0f, q = 0.0f;
        #pragma unroll
        for (int w = 0; w < 8; w++) {
            s += ssum[w * D + t];
            q += ssq [w * D + t];
        }
        atomicAdd(&g_bnsum[off + t],     s);
        atomicAdd(&g_bnsum[off + D + t], q);
    }
}

// Final BN+ReLU from g_buf2 (stats g_bnsum[128..255]) -> d_out. float4.
__global__ void k_apply(float4* __restrict__ out,
                        const float* __restrict__ gamma,
                        const float* __restrict__ beta) {
    __shared__ float s_sc[D], s_sh[D];
    int t = threadIdx.x;
    if (t < D) {
        float inv_n = 1.0f / (float)NN;
        float mu  = g_bnsum[128 + t] * inv_n;
        float var = g_bnsum[192 + t] * inv_n - mu * mu;
        float sc  = gamma[t] * rsqrtf(var + BN_EPS);
        s_sc[t] = sc;
        s_sh[t] = beta[t] - mu * sc;
    }
    __syncthreads();
    const float4* __restrict__ in = (const float4*)g_buf2;
    size_t total  = (size_t)NN * (D / 4);
    size_t stride = (size_t)gridDim.x * blockDim.x;
    for (size_t i = (size_t)blockIdx.x * blockDim.x + t; i < total; i += stride) {
        int f = ((int)i & 15) * 4;
        float4 v = in[i];
        v.x = fmaxf(fmaf(v.x, s_sc[f],     s_sh[f]),     0.0f);
        v.y = fmaxf(fmaf(v.y, s_sc[f + 1], s_sh[f + 1]), 0.0f);
        v.z = fmaxf(fmaf(v.z, s_sc[f + 2], s_sh[f + 2]), 0.0f);
        v.w = fmaxf(fmaf(v.w, s_sc[f + 3], s_sh[f + 3]), 0.0f);
        out[i] = v;
    }
}

// ---------------- launch ----------------
extern "C" void kernel_launch(void* const* d_in, const int* in_sizes, int n_in,
                              void* d_out, int out_size) {
    const float* x   = (const float*)d_in[0];
    const int*   ei  = (const int*)  d_in[1];
    const float* W1  = (const float*)d_in[2];
    const float* b1  = (const float*)d_in[3];
    const float* ga1 = (const float*)d_in[4];
    const float* be1 = (const float*)d_in[5];
    const float* W2  = (const float*)d_in[6];
    const float* b2  = (const float*)d_in[7];
    const float* ga2 = (const float*)d_in[8];
    const float* be2 = (const float*)d_in[9];
    float* out = (float*)d_out;

    const int4* src4 = (const int4*)ei;         // edge_index[0]
    const int4* dst4 = (const int4*)(ei + EE);  // edge_index[1]

    const int TB = 256;
    const int WORK_BLKS = 1480;  // grid-stride for gemm/agg

    // CSR build
    k_init   <<<256, TB>>>();
    k_count  <<<1024, TB>>>(dst4);
    k_scan   <<<NCH, 1024>>>();
    k_scatter<<<1024, TB>>>(src4, dst4);

    // Layer 1
    k_gemm <<<WORK_BLKS, TB>>>(x, W1, nullptr, nullptr, 0);   // g_h = fp16(x@W1)
    k_agg  <<<WORK_BLKS, TB>>>(b1, 0);                        // buf2 = agg(g_h)+b1, stats->[0:128)

    // Layer 2 (BN1+ReLU fused into GEMM input)
    k_gemm <<<WORK_BLKS, TB>>>(nullptr, W2, ga1, be1, 1);     // g_h = fp16(relu(bn(buf2))@W2)
    k_agg  <<<WORK_BLKS, TB>>>(b2, 128);                      // buf2 = agg(g_h)+b2, stats->[128:256)

    // Output
    k_apply<<<2048, TB>>>((float4*)out, ga2, be2);
}

// round 8
// speedup vs baseline: 1.1216x; 1.1216x over previous
#include <cuda_runtime.h>

// Problem constants (fixed by the dataset)
#define NN 100000
#define EE 1600000
#define D  64
#define BN_EPS 1e-5f
#define NCH 98   // ceil(NN / 1024)

// ---------------- scratch (static device globals; no allocation) ----------------
__device__ int   g_deg[NN];
__device__ float g_dis[NN];
__device__ int   g_rowptr[NN + 1];
__device__ int   g_fill[NN];               // seeded with rowptr; atomic bump = slot
__device__ int   g_psum[128];              // lookback aggregates (bit31 = ready)
__device__ int   g_col[EE];                // CSR column (src) only — no weights
__device__ __align__(16) float g_buf1[(size_t)NN * D];  // h' = dis[n] * (X@W)[n]
__device__ __align__(16) float g_buf2[(size_t)NN * D];  // aggregation outputs
__device__ float g_bnsum[4 * D];  // [sum1 | sq1 | sum2 | sq2]

// ---------------- kernels ----------------

// Reset per-call state: deg=1 (self loop), psum flags, bn accumulators.
__global__ void k_init() {
    int stride = gridDim.x * blockDim.x;
    for (int i = blockIdx.x * blockDim.x + threadIdx.x; i < NN; i += stride)
        g_deg[i] = 1;
    if (blockIdx.x == 0 && threadIdx.x < 4 * D) g_bnsum[threadIdx.x] = 0.0f;
    if (blockIdx.x == 0 && threadIdx.x < 128)   g_psum[threadIdx.x]  = 0;
    if (blockIdx.x == 0 && threadIdx.x == 0)    g_rowptr[NN] = EE;
}

// In-degree histogram over dst (int4 vectorized; EE % 4 == 0). No-return atomics.
__global__ void k_count(const int4* __restrict__ dst4) {
    int stride = gridDim.x * blockDim.x;
    for (int e = blockIdx.x * blockDim.x + threadIdx.x; e < EE / 4; e += stride) {
        int4 d = __ldg(&dst4[e]);
        atomicAdd(&g_deg[d.x], 1);
        atomicAdd(&g_deg[d.y], 1);
        atomicAdd(&g_deg[d.z], 1);
        atomicAdd(&g_deg[d.w], 1);
    }
}

// Single-pass scan with decoupled lookback (98 blocks, all resident -> safe).
// Produces: g_dis = rsqrt(deg), g_rowptr = exclusive scan of (deg-1),
// g_fill seeded with the same value (scatter bumps it directly).
__global__ void k_scan() {
    __shared__ int s[1024];
    __shared__ int s_off[128];
    int t = threadIdx.x, b = blockIdx.x;
    int idx = b * 1024 + t;
    int d = 0;
    if (idx < NN) {
        int dg = g_deg[idx];
        g_dis[idx] = rsqrtf((float)dg);
        d = dg - 1;  // edge count only (self loop handled separately)
    }
    s[t] = d;
    __syncthreads();
    // Inclusive Hillis-Steele scan within the block.
    #pragma unroll
    for (int off = 1; off < 1024; off <<= 1) {
        int v = (t >= off) ? s[t - off] : 0;
        __syncthreads();
        s[t] += v;
        __syncthreads();
    }
    // Publish aggregate (payload inside the word; bit31 = ready flag).
    if (t == 0) atomicExch(&g_psum[b], s[1023] | 0x80000000);
    // Poll all predecessor aggregates in parallel (one per thread).
    int part = 0;
    if (t < b) {
        int v;
        do { v = *(volatile int*)&g_psum[t]; } while (!(v & 0x80000000));
        part = v & 0x7fffffff;
    }
    if (t < 128) s_off[t] = part;
    __syncthreads();
    #pragma unroll
    for (int o = 64; o > 0; o >>= 1) {
        if (t < o) s_off[t] += s_off[t + o];
        __syncthreads();
    }
    if (idx < NN) {
        int rp = s_off[0] + s[t] - d;  // exclusive
        g_rowptr[idx] = rp;
        g_fill[idx]   = rp;
    }
}

// Scatter edges into CSR buckets. Per edge: ONE returning atomic + ONE 4B store.
__global__ void k_scatter(const int4* __restrict__ src4, const int4* __restrict__ dst4) {
    int stride = gridDim.x * blockDim.x;
    for (int e = blockIdx.x * blockDim.x + threadIdx.x; e < EE / 4; e += stride) {
        int4 sv = __ldg(&src4[e]);
        int4 dv = __ldg(&dst4[e]);
        int o0 = atomicAdd(&g_fill[dv.x], 1);
        int o1 = atomicAdd(&g_fill[dv.y], 1);
        int o2 = atomicAdd(&g_fill[dv.z], 1);
        int o3 = atomicAdd(&g_fill[dv.w], 1);
        g_col[o0] = sv.x;
        g_col[o1] = sv.y;
        g_col[o2] = sv.z;
        g_col[o3] = sv.w;
    }
}

// GEMM: g_buf1 = dis[row] * (X @ W).  mode 0: X = x_ext.  mode 1: X = g_buf2
// with fused BatchNorm(stats g_bnsum[0..127]) + ReLU on the input read.
// One warp per row (grid-stride); lane owns 2 output cols; W in shared.
__global__ void k_gemm(const float* __restrict__ X_ext,
                       const float* __restrict__ W,
                       const float* __restrict__ gamma,
                       const float* __restrict__ beta,
                       int mode) {
    __shared__ __align__(16) float ws[D * D];
    __shared__ float s_sc[D], s_sh[D];
    int t = threadIdx.x;
    for (int i = t; i < D * D / 4; i += blockDim.x)
        ((float4*)ws)[i] = ((const float4*)W)[i];
    if (mode == 1 && t < D) {
        float inv_n = 1.0f / (float)NN;
        float mu  = g_bnsum[t] * inv_n;
        float var = g_bnsum[D + t] * inv_n - mu * mu;
        float sc  = gamma[t] * rsqrtf(var + BN_EPS);
        s_sc[t] = sc;
        s_sh[t] = beta[t] - mu * sc;
    }
    __syncthreads();

    int warp = t >> 5, lane = t & 31;
    int wpb = blockDim.x >> 5;
    int stride = gridDim.x * wpb;
    const float* X = (mode == 0) ? X_ext : g_buf2;
    for (int row = blockIdx.x * wpb + warp; row < NN; row += stride) {
        float2 xr = ((const float2*)(X + (size_t)row * D))[lane];
        if (mode == 1) {
            xr.x = fmaxf(fmaf(xr.x, s_sc[2 * lane],     s_sh[2 * lane]),     0.0f);
            xr.y = fmaxf(fmaf(xr.y, s_sc[2 * lane + 1], s_sh[2 * lane + 1]), 0.0f);
        }
        float2 acc = make_float2(0.0f, 0.0f);
        #pragma unroll
        for (int k = 0; k < D; k++) {
            float xv = __shfl_sync(0xffffffffu, (k & 1) ? xr.y : xr.x, k >> 1);
            float2 wv = ((const float2*)(ws + k * D))[lane];
            acc.x = fmaf(xv, wv.x, acc.x);
            acc.y = fmaf(xv, wv.y, acc.y);
        }
        float dr = g_dis[row];
        acc.x *= dr;
        acc.y *= dr;
        ((float2*)(g_buf1 + (size_t)row * D))[lane] = acc;
    }
}

// Pull aggregation (weight-free inner loop) with FUSED BN stats:
//   g_buf2[n] = bias + dis[n] * ( h'[n] + sum_e h'[col[e]] )
// where h' = dis * h was pre-scaled by the GEMM. One warp per node
// (grid-stride), lane owns 2 features, no float atomics in the hot loop.
// Per-feature sum/sumsq reduced per block, one atomic per feature.
// Requires blockDim == 256.
__global__ void k_agg(const float* __restrict__ bias, int off) {
    __shared__ float ssum[8 * D], ssq[8 * D];
    int t = threadIdx.x;
    int warp = t >> 5, lane = t & 31;
    int stride = gridDim.x * 8;
    const float2* __restrict__ H2 = (const float2*)g_buf1;
    float2 b = ((const float2*)bias)[lane];
    float2 ts = make_float2(0.0f, 0.0f);
    float2 tq = make_float2(0.0f, 0.0f);
    for (int n = blockIdx.x * 8 + warp; n < NN; n += stride) {
        float dn = g_dis[n];
        float2 acc = __ldg(&H2[(size_t)n * 32 + lane]);  // self term h'[n]
        int s0 = g_rowptr[n], e0 = g_rowptr[n + 1];
        #pragma unroll 8
        for (int i = s0; i < e0; i++) {
            int col = __ldg(&g_col[i]);                  // uniform across warp
            float2 v = __ldg(&H2[(size_t)col * 32 + lane]);
            acc.x += v.x;
            acc.y += v.y;
        }
        float2 o = make_float2(fmaf(dn, acc.x, b.x), fmaf(dn, acc.y, b.y));
        ((float2*)(g_buf2 + (size_t)n * D))[lane] = o;
        ts.x += o.x;
        ts.y += o.y;
        tq.x = fmaf(o.x, o.x, tq.x);
        tq.y = fmaf(o.y, o.y, tq.y);
    }
    ssum[warp * D + 2 * lane]     = ts.x;
    ssum[warp * D + 2 * lane + 1] = ts.y;
    ssq [warp * D + 2 * lane]     = tq.x;
    ssq [warp * D + 2 * lane + 1] = tq.y;
    __syncthreads();
    if (t < D) {
        float s = 0.0f, q = 0.0f;
        #pragma unroll
        for (int w = 0; w < 8; w++) {
            s += ssum[w * D + t];
            q += ssq [w * D + t];
        }
        atomicAdd(&g_bnsum[off + t],     s);
        atomicAdd(&g_bnsum[off + D + t], q);
    }
}

// Final BN+ReLU from g_buf2 (stats g_bnsum[128..255]) -> d_out. float4.
__global__ void k_apply(float4* __restrict__ out,
                        const float* __restrict__ gamma,
                        const float* __restrict__ beta) {
    __shared__ float s_sc[D], s_sh[D];
    int t = threadIdx.x;
    if (t < D) {
        float inv_n = 1.0f / (float)NN;
        float mu  = g_bnsum[128 + t] * inv_n;
        float var = g_bnsum[192 + t] * inv_n - mu * mu;
        float sc  = gamma[t] * rsqrtf(var + BN_EPS);
        s_sc[t] = sc;
        s_sh[t] = beta[t] - mu * sc;
    }
    __syncthreads();
    const float4* __restrict__ in = (const float4*)g_buf2;
    size_t total  = (size_t)NN * (D / 4);
    size_t stride = (size_t)gridDim.x * blockDim.x;
    for (size_t i = (size_t)blockIdx.x * blockDim.x + t; i < total; i += stride) {
        int f = ((int)i & 15) * 4;
        float4 v = in[i];
        v.x = fmaxf(fmaf(v.x, s_sc[f],     s_sh[f]),     0.0f);
        v.y = fmaxf(fmaf(v.y, s_sc[f + 1], s_sh[f + 1]), 0.0f);
        v.z = fmaxf(fmaf(v.z, s_sc[f + 2], s_sh[f + 2]), 0.0f);
        v.w = fmaxf(fmaf(v.w, s_sc[f + 3], s_sh[f + 3]), 0.0f);
        out[i] = v;
    }
}

// ---------------- launch ----------------
extern "C" void kernel_launch(void* const* d_in, const int* in_sizes, int n_in,
                              void* d_out, int out_size) {
    const float* x   = (const float*)d_in[0];
    const int*   ei  = (const int*)  d_in[1];
    const float* W1  = (const float*)d_in[2];
    const float* b1  = (const float*)d_in[3];
    const float* ga1 = (const float*)d_in[4];
    const float* be1 = (const float*)d_in[5];
    const float* W2  = (const float*)d_in[6];
    const float* b2  = (const float*)d_in[7];
    const float* ga2 = (const float*)d_in[8];
    const float* be2 = (const float*)d_in[9];
    float* out = (float*)d_out;

    const int4* src4 = (const int4*)ei;         // edge_index[0]
    const int4* dst4 = (const int4*)(ei + EE);  // edge_index[1]

    const int TB = 256;
    const int WORK_BLKS = 1480;  // grid-stride for gemm/agg

    // CSR build
    k_init   <<<256, TB>>>();
    k_count  <<<2048, TB>>>(dst4);
    k_scan   <<<NCH, 1024>>>();
    k_scatter<<<2048, TB>>>(src4, dst4);

    // Layer 1
    k_gemm <<<WORK_BLKS, TB>>>(x, W1, nullptr, nullptr, 0);   // buf1 = dis*(x@W1)
    k_agg  <<<WORK_BLKS, TB>>>(b1, 0);                        // buf2 = agg+b1, stats->[0:128)

    // Layer 2 (BN1+ReLU fused into GEMM input)
    k_gemm <<<WORK_BLKS, TB>>>(nullptr, W2, ga1, be1, 1);     // buf1 = dis*(relu(bn(buf2))@W2)
    k_agg  <<<WORK_BLKS, TB>>>(b2, 128);                      // buf2 = agg+b2, stats->[128:256)

    // Output
    k_apply<<<2048, TB>>>((float4*)out, ga2, be2);
}

// round 9
// speedup vs baseline: 1.2653x; 1.1282x over previous
#include <cuda_runtime.h>

// Problem constants (fixed by the dataset)
#define NN 100000
#define EE 1600000
#define D  64
#define BN_EPS 1e-5f
#define NCH 98   // ceil(NN / 1024)

// ---------------- scratch (static device globals; no allocation) ----------------
// Self-cleaning invariant: at the START of every kernel_launch call,
//   g_deg == 0 (static zero-init on call 1; reset by k_apply thereafter)
// g_psum / g_bnsum are reset by block 0 of k_count (first kernel of the call)
// before their consumers (k_scan / k_agg / k_gemm / k_apply) run.
__device__ int   g_deg[NN];
__device__ float g_dis[NN];
__device__ int   g_rowptr[NN + 1];
__device__ int   g_fill[NN];               // seeded with rowptr; atomic bump = slot
__device__ int   g_psum[128];              // lookback aggregates (bit31 = ready)
__device__ int   g_col[EE];                // CSR column (src) only — no weights
__device__ __align__(16) float g_buf1[(size_t)NN * D];  // h' = dis[n] * (X@W)[n]
__device__ __align__(16) float g_buf2[(size_t)NN * D];  // aggregation outputs
__device__ float g_bnsum[4 * D];  // [sum1 | sq1 | sum2 | sq2]

// ---------------- kernels ----------------

// Edge histogram over dst (int4; EE % 4 == 0). deg counts EDGES only (no self
// loop; scan adds +1). Block 0 also resets psum/bnsum for this call.
__global__ void k_count(const int4* __restrict__ dst4) {
    if (blockIdx.x == 0) {
        int t = threadIdx.x;
        if (t < 4 * D) g_bnsum[t] = 0.0f;   // 256 floats
        if (t < 128)   g_psum[t]  = 0;
    }
    int stride = gridDim.x * blockDim.x;
    for (int e = blockIdx.x * blockDim.x + threadIdx.x; e < EE / 4; e += stride) {
        int4 d = __ldg(&dst4[e]);
        atomicAdd(&g_deg[d.x], 1);
        atomicAdd(&g_deg[d.y], 1);
        atomicAdd(&g_deg[d.z], 1);
        atomicAdd(&g_deg[d.w], 1);
    }
}

// Single-pass scan with decoupled lookback (98 blocks, all resident -> safe).
// deg holds edge counts (self loop NOT included); true degree = deg+1.
// Produces: g_dis = rsqrt(deg+1), g_rowptr = exclusive scan of deg,
// g_fill seeded with rowptr, g_rowptr[NN] = EE.
__global__ void k_scan() {
    __shared__ int s[1024];
    __shared__ int s_off[128];
    int t = threadIdx.x, b = blockIdx.x;
    int idx = b * 1024 + t;
    int d = 0;
    if (idx < NN) {
        d = g_deg[idx];                      // edges into idx
        g_dis[idx] = rsqrtf((float)(d + 1)); // +1 self loop
    }
    s[t] = d;
    __syncthreads();
    // Inclusive Hillis-Steele scan within the block.
    #pragma unroll
    for (int off = 1; off < 1024; off <<= 1) {
        int v = (t >= off) ? s[t - off] : 0;
        __syncthreads();
        s[t] += v;
        __syncthreads();
    }
    // Publish aggregate (payload inside the word; bit31 = ready flag).
    if (t == 0) atomicExch(&g_psum[b], s[1023] | 0x80000000);
    // Poll all predecessor aggregates in parallel (one per thread).
    int part = 0;
    if (t < b) {
        int v;
        do { v = *(volatile int*)&g_psum[t]; } while (!(v & 0x80000000));
        part = v & 0x7fffffff;
    }
    if (t < 128) s_off[t] = part;
    __syncthreads();
    #pragma unroll
    for (int o = 64; o > 0; o >>= 1) {
        if (t < o) s_off[t] += s_off[t + o];
        __syncthreads();
    }
    if (idx < NN) {
        int rp = s_off[0] + s[t] - d;  // exclusive
        g_rowptr[idx] = rp;
        g_fill[idx]   = rp;
    }
    if (b == NCH - 1 && t == 1023) g_rowptr[NN] = s_off[0] + s[1023];  // == EE
}

// Scatter edges into CSR buckets. Per edge: ONE returning atomic + ONE 4B store.
__global__ void k_scatter(const int4* __restrict__ src4, const int4* __restrict__ dst4) {
    int stride = gridDim.x * blockDim.x;
    for (int e = blockIdx.x * blockDim.x + threadIdx.x; e < EE / 4; e += stride) {
        int4 sv = __ldg(&src4[e]);
        int4 dv = __ldg(&dst4[e]);
        int o0 = atomicAdd(&g_fill[dv.x], 1);
        int o1 = atomicAdd(&g_fill[dv.y], 1);
        int o2 = atomicAdd(&g_fill[dv.z], 1);
        int o3 = atomicAdd(&g_fill[dv.w], 1);
        g_col[o0] = sv.x;
        g_col[o1] = sv.y;
        g_col[o2] = sv.z;
        g_col[o3] = sv.w;
    }
}

// GEMM: g_buf1 = dis[row] * (X @ W).  mode 0: X = x_ext.  mode 1: X = g_buf2
// with fused BatchNorm(stats g_bnsum[0..127]) + ReLU on the input read.
// One warp per row (grid-stride); lane owns 2 output cols; W in shared.
__global__ void k_gemm(const float* __restrict__ X_ext,
                       const float* __restrict__ W,
                       const float* __restrict__ gamma,
                       const float* __restrict__ beta,
                       int mode) {
    __shared__ __align__(16) float ws[D * D];
    __shared__ float s_sc[D], s_sh[D];
    int t = threadIdx.x;
    for (int i = t; i < D * D / 4; i += blockDim.x)
        ((float4*)ws)[i] = ((const float4*)W)[i];
    if (mode == 1 && t < D) {
        float inv_n = 1.0f / (float)NN;
        float mu  = g_bnsum[t] * inv_n;
        float var = g_bnsum[D + t] * inv_n - mu * mu;
        float sc  = gamma[t] * rsqrtf(var + BN_EPS);
        s_sc[t] = sc;
        s_sh[t] = beta[t] - mu * sc;
    }
    __syncthreads();

    int warp = t >> 5, lane = t & 31;
    int wpb = blockDim.x >> 5;
    int stride = gridDim.x * wpb;
    const float* X = (mode == 0) ? X_ext : g_buf2;
    for (int row = blockIdx.x * wpb + warp; row < NN; row += stride) {
        float2 xr = ((const float2*)(X + (size_t)row * D))[lane];
        if (mode == 1) {
            xr.x = fmaxf(fmaf(xr.x, s_sc[2 * lane],     s_sh[2 * lane]),     0.0f);
            xr.y = fmaxf(fmaf(xr.y, s_sc[2 * lane + 1], s_sh[2 * lane + 1]), 0.0f);
        }
        float2 acc = make_float2(0.0f, 0.0f);
        #pragma unroll
        for (int k = 0; k < D; k++) {
            float xv = __shfl_sync(0xffffffffu, (k & 1) ? xr.y : xr.x, k >> 1);
            float2 wv = ((const float2*)(ws + k * D))[lane];
            acc.x = fmaf(xv, wv.x, acc.x);
            acc.y = fmaf(xv, wv.y, acc.y);
        }
        float dr = g_dis[row];
        acc.x *= dr;
        acc.y *= dr;
        ((float2*)(g_buf1 + (size_t)row * D))[lane] = acc;
    }
}

// Pull aggregation: HALF-WARP per node (float4 lanes) -> 2 independent edge
// streams per warp (2x MLP, ~1.8x fewer issue slots per edge).
//   g_buf2[n] = bias + dis[n] * ( h'[n] + sum_e h'[col[e]] )
// FUSED BN stats: per-feature sum/sumsq, halves combined via shfl, block
// reduce, one atomic per feature. Requires blockDim == 256, NN even.
__global__ void k_agg(const float* __restrict__ bias, int off) {
    __shared__ float ssum[8 * D], ssq[8 * D];
    int t = threadIdx.x;
    int warp = t >> 5, lane = t & 31;
    int half = lane >> 4, hl = lane & 15;     // half-warp id, lane within half
    int gwarp  = blockIdx.x * 8 + warp;
    int nwarps = gridDim.x * 8;
    const float4* __restrict__ H4 = (const float4*)g_buf1;
    float4 b = ((const float4*)bias)[hl];
    float4 ts = make_float4(0.f, 0.f, 0.f, 0.f);
    float4 tq = make_float4(0.f, 0.f, 0.f, 0.f);
    for (int pair = gwarp; pair < NN / 2; pair += nwarps) {
        int n = 2 * pair + half;
        float dn = g_dis[n];
        float4 acc = __ldg(&H4[(size_t)n * 16 + hl]);   // self term h'[n]
        int s0 = g_rowptr[n], e0 = g_rowptr[n + 1];
        #pragma unroll 4
        for (int i = s0; i < e0; i++) {
            int col = __ldg(&g_col[i]);                 // broadcast within half
            float4 v = __ldg(&H4[(size_t)col * 16 + hl]);
            acc.x += v.x; acc.y += v.y; acc.z += v.z; acc.w += v.w;
        }
        float4 o;
        o.x = fmaf(dn, acc.x, b.x);
        o.y = fmaf(dn, acc.y, b.y);
        o.z = fmaf(dn, acc.z, b.z);
        o.w = fmaf(dn, acc.w, b.w);
        ((float4*)g_buf2)[(size_t)n * 16 + hl] = o;
        ts.x += o.x; ts.y += o.y; ts.z += o.z; ts.w += o.w;
        tq.x = fmaf(o.x, o.x, tq.x);
        tq.y = fmaf(o.y, o.y, tq.y);
        tq.z = fmaf(o.z, o.z, tq.z);
        tq.w = fmaf(o.w, o.w, tq.w);
    }
    __syncwarp();
    // Combine the two halves (same features) with shuffles.
    ts.x += __shfl_down_sync(0xffffffffu, ts.x, 16);
    ts.y += __shfl_down_sync(0xffffffffu, ts.y, 16);
    ts.z += __shfl_down_sync(0xffffffffu, ts.z, 16);
    ts.w += __shfl_down_sync(0xffffffffu, ts.w, 16);
    tq.x += __shfl_down_sync(0xffffffffu, tq.x, 16);
    tq.y += __shfl_down_sync(0xffffffffu, tq.y, 16);
    tq.z += __shfl_down_sync(0xffffffffu, tq.z, 16);
    tq.w += __shfl_down_sync(0xffffffffu, tq.w, 16);
    if (half == 0) {
        ((float4*)(ssum + warp * D))[hl] = ts;
        ((float4*)(ssq  + warp * D))[hl] = tq;
    }
    __syncthreads();
    if (t < D) {
        float s = 0.0f, q = 0.0f;
        #pragma unroll
        for (int w = 0; w < 8; w++) {
            s += ssum[w * D + t];
            q += ssq [w * D + t];
        }
        atomicAdd(&g_bnsum[off + t],     s);
        atomicAdd(&g_bnsum[off + D + t], q);
    }
}

// Final BN+ReLU from g_buf2 (stats g_bnsum[128..255]) -> d_out. float4.
// Also resets g_deg for the NEXT call (no reader of g_deg in this kernel).
__global__ void k_apply(float4* __restrict__ out,
                        const float* __restrict__ gamma,
                        const float* __restrict__ beta) {
    __shared__ float s_sc[D], s_sh[D];
    int t = threadIdx.x;
    if (t < D) {
        float inv_n = 1.0f / (float)NN;
        float mu  = g_bnsum[128 + t] * inv_n;
        float var = g_bnsum[192 + t] * inv_n - mu * mu;
        float sc  = gamma[t] * rsqrtf(var + BN_EPS);
        s_sc[t] = sc;
        s_sh[t] = beta[t] - mu * sc;
    }
    __syncthreads();
    const float4* __restrict__ in = (const float4*)g_buf2;
    size_t total  = (size_t)NN * (D / 4);
    size_t stride = (size_t)gridDim.x * blockDim.x;
    for (size_t i = (size_t)blockIdx.x * blockDim.x + t; i < total; i += stride) {
        int f = ((int)i & 15) * 4;
        float4 v = in[i];
        v.x = fmaxf(fmaf(v.x, s_sc[f],     s_sh[f]),     0.0f);
        v.y = fmaxf(fmaf(v.y, s_sc[f + 1], s_sh[f + 1]), 0.0f);
        v.z = fmaxf(fmaf(v.z, s_sc[f + 2], s_sh[f + 2]), 0.0f);
        v.w = fmaxf(fmaf(v.w, s_sc[f + 3], s_sh[f + 3]), 0.0f);
        out[i] = v;
    }
    // Self-clean for next call.
    for (int i = blockIdx.x * blockDim.x + t; i < NN; i += (int)stride)
        g_deg[i] = 0;
}

// ---------------- launch ----------------
extern "C" void kernel_launch(void* const* d_in, const int* in_sizes, int n_in,
                              void* d_out, int out_size) {
    const float* x   = (const float*)d_in[0];
    const int*   ei  = (const int*)  d_in[1];
    const float* W1  = (const float*)d_in[2];
    const float* b1  = (const float*)d_in[3];
    const float* ga1 = (const float*)d_in[4];
    const float* be1 = (const float*)d_in[5];
    const float* W2  = (const float*)d_in[6];
    const float* b2  = (const float*)d_in[7];
    const float* ga2 = (const float*)d_in[8];
    const float* be2 = (const float*)d_in[9];
    float* out = (float*)d_out;

    const int4* src4 = (const int4*)ei;         // edge_index[0]
    const int4* dst4 = (const int4*)(ei + EE);  // edge_index[1]

    const int TB = 256;
    const int WORK_BLKS = 1480;  // grid-stride for gemm/agg

    // CSR build (k_count also resets psum/bnsum for this call)
    k_count  <<<2048, TB>>>(dst4);
    k_scan   <<<NCH, 1024>>>();
    k_scatter<<<2048, TB>>>(src4, dst4);

    // Layer 1
    k_gemm <<<WORK_BLKS, TB>>>(x, W1, nullptr, nullptr, 0);   // buf1 = dis*(x@W1)
    k_agg  <<<WORK_BLKS, TB>>>(b1, 0);                        // buf2 = agg+b1, stats->[0:128)

    // Layer 2 (BN1+ReLU fused into GEMM input)
    k_gemm <<<WORK_BLKS, TB>>>(nullptr, W2, ga1, be1, 1);     // buf1 = dis*(relu(bn(buf2))@W2)
    k_agg  <<<WORK_BLKS, TB>>>(b2, 128);                      // buf2 = agg+b2, stats->[128:256)

    // Output (+ self-clean g_deg for next call)
    k_apply<<<2048, TB>>>((float4*)out, ga2, be2);
}

// round 11
// speedup vs baseline: 1.9203x; 1.5176x over previous
#include <cuda_runtime.h>

// Problem constants (fixed by the dataset)
#define NN 100000
#define EE 1600000
#define D  64
#define BN_EPS 1e-5f
#define NCH 98   // ceil(NN / 1024)
#define TM 64    // GEMM tile rows per block
#define XS 65    // padded row stride for X tile in shared

// ---------------- scratch (static device globals; no allocation) ----------------
// Self-cleaning invariant: at the START of every kernel_launch call,
//   g_deg == 0 (static zero-init on call 1; reset by k_apply thereafter)
// g_psum / g_bnsum are reset by block 0 of k_count (first kernel of the call)
// before their consumers (k_scan / k_agg / k_gemm / k_apply) run.
__device__ int   g_deg[NN];
__device__ float g_dis[NN];
__device__ int   g_rowptr[NN + 1];
__device__ int   g_fill[NN];               // seeded with rowptr; atomic bump = slot
__device__ int   g_psum[128];              // lookback aggregates (bit31 = ready)
__device__ int   g_col[EE];                // CSR column (src) only — no weights
__device__ __align__(16) float g_buf1[(size_t)NN * D];  // h' = dis[n] * (X@W)[n]
__device__ __align__(16) float g_buf2[(size_t)NN * D];  // aggregation outputs
__device__ float g_bnsum[4 * D];  // [sum1 | sq1 | sum2 | sq2]

// ---------------- kernels ----------------

// Edge histogram over dst (int4; EE % 4 == 0). deg counts EDGES only (no self
// loop; scan adds +1). Block 0 also resets psum/bnsum for this call.
__global__ void k_count(const int4* __restrict__ dst4) {
    if (blockIdx.x == 0) {
        int t = threadIdx.x;
        if (t < 4 * D) g_bnsum[t] = 0.0f;   // 256 floats
        if (t < 128)   g_psum[t]  = 0;
    }
    int stride = gridDim.x * blockDim.x;
    for (int e = blockIdx.x * blockDim.x + threadIdx.x; e < EE / 4; e += stride) {
        int4 d = __ldg(&dst4[e]);
        atomicAdd(&g_deg[d.x], 1);
        atomicAdd(&g_deg[d.y], 1);
        atomicAdd(&g_deg[d.z], 1);
        atomicAdd(&g_deg[d.w], 1);
    }
}

// Single-pass scan with decoupled lookback (98 blocks, all resident -> safe).
// deg holds edge counts (self loop NOT included); true degree = deg+1.
// Produces: g_dis = rsqrt(deg+1), g_rowptr = exclusive scan of deg,
// g_fill seeded with rowptr, g_rowptr[NN] = EE.
__global__ void k_scan() {
    __shared__ int s[1024];
    __shared__ int s_off[128];
    int t = threadIdx.x, b = blockIdx.x;
    int idx = b * 1024 + t;
    int d = 0;
    if (idx < NN) {
        d = g_deg[idx];                      // edges into idx
        g_dis[idx] = rsqrtf((float)(d + 1)); // +1 self loop
    }
    s[t] = d;
    __syncthreads();
    // Inclusive Hillis-Steele scan within the block.
    #pragma unroll
    for (int off = 1; off < 1024; off <<= 1) {
        int v = (t >= off) ? s[t - off] : 0;
        __syncthreads();
        s[t] += v;
        __syncthreads();
    }
    // Publish aggregate (payload inside the word; bit31 = ready flag).
    if (t == 0) atomicExch(&g_psum[b], s[1023] | 0x80000000);
    // Poll all predecessor aggregates in parallel (one per thread).
    int part = 0;
    if (t < b) {
        int v;
        do { v = *(volatile int*)&g_psum[t]; } while (!(v & 0x80000000));
        part = v & 0x7fffffff;
    }
    if (t < 128) s_off[t] = part;
    __syncthreads();
    #pragma unroll
    for (int o = 64; o > 0; o >>= 1) {
        if (t < o) s_off[t] += s_off[t + o];
        __syncthreads();
    }
    if (idx < NN) {
        int rp = s_off[0] + s[t] - d;  // exclusive
        g_rowptr[idx] = rp;
        g_fill[idx]   = rp;
    }
    if (b == NCH - 1 && t == 1023) g_rowptr[NN] = s_off[0] + s[1023];  // == EE
}

// Scatter edges into CSR buckets. Per edge: ONE returning atomic + ONE 4B store.
__global__ void k_scatter(const int4* __restrict__ src4, const int4* __restrict__ dst4) {
    int stride = gridDim.x * blockDim.x;
    for (int e = blockIdx.x * blockDim.x + threadIdx.x; e < EE / 4; e += stride) {
        int4 sv = __ldg(&src4[e]);
        int4 dv = __ldg(&dst4[e]);
        int o0 = atomicAdd(&g_fill[dv.x], 1);
        int o1 = atomicAdd(&g_fill[dv.y], 1);
        int o2 = atomicAdd(&g_fill[dv.z], 1);
        int o3 = atomicAdd(&g_fill[dv.w], 1);
        g_col[o0] = sv.x;
        g_col[o1] = sv.y;
        g_col[o2] = sv.z;
        g_col[o3] = sv.w;
    }
}

// Register-blocked GEMM: g_buf1 = dis[row] * (X @ W).
// mode 0: X = x_ext.  mode 1: X = g_buf2 with BatchNorm+ReLU fused into the
// shared-memory staging of X.
// Block = 256 threads (16x16), tile = 64 rows x 64 cols, 4x4 outputs/thread.
// Per k-step/thread: 4x LDS.32 (X, pad-65) + 1x LDS.128 (W) + 16 FMA.
__global__ __launch_bounds__(256) void k_gemm(
        const float* __restrict__ X_ext,
        const float* __restrict__ W,
        const float* __restrict__ gamma,
        const float* __restrict__ beta,
        int mode) {
    __shared__ float Xs[TM * XS];
    __shared__ __align__(16) float Ws[D * D];
    __shared__ float s_sc[D], s_sh[D];
    int t = threadIdx.x;

    for (int i = t; i < D * D / 4; i += 256)
        ((float4*)Ws)[i] = ((const float4*)W)[i];
    if (mode == 1 && t < D) {
        float inv_n = 1.0f / (float)NN;
        float mu  = g_bnsum[t] * inv_n;
        float var = g_bnsum[D + t] * inv_n - mu * mu;
        float sc  = gamma[t] * rsqrtf(var + BN_EPS);
        s_sc[t] = sc;
        s_sh[t] = beta[t] - mu * sc;
    }
    __syncthreads();

    int row0 = blockIdx.x * TM;
    bool full = (row0 + TM <= NN);
    const float* X = (mode == 0) ? X_ext : g_buf2;

    // Stage X tile (64x64) into shared; BN+ReLU fused here in mode 1.
    #pragma unroll
    for (int i = t; i < TM * D / 4; i += 256) {
        int r  = i >> 4;            // 16 float4 per row
        int c4 = (i & 15) * 4;
        int gr = row0 + r;
        if (!full && gr >= NN) gr = NN - 1;  // clamp (store guarded later)
        float4 v = __ldg(&((const float4*)(X + (size_t)gr * D))[i & 15]);
        if (mode == 1) {
            v.x = fmaxf(fmaf(v.x, s_sc[c4],     s_sh[c4]),     0.0f);
            v.y = fmaxf(fmaf(v.y, s_sc[c4 + 1], s_sh[c4 + 1]), 0.0f);
            v.z = fmaxf(fmaf(v.z, s_sc[c4 + 2], s_sh[c4 + 2]), 0.0f);
            v.w = fmaxf(fmaf(v.w, s_sc[c4 + 3], s_sh[c4 + 3]), 0.0f);
        }
        float* xp = Xs + r * XS + c4;
        xp[0] = v.x; xp[1] = v.y; xp[2] = v.z; xp[3] = v.w;
    }
    __syncthreads();

    int tx = t & 15, ty = t >> 4;
    int r0 = ty * 4, c0 = tx * 4;
    float acc[4][4] = {};
    #pragma unroll 8
    for (int k = 0; k < D; k++) {
        float a0 = Xs[(r0 + 0) * XS + k];
        float a1 = Xs[(r0 + 1) * XS + k];
        float a2 = Xs[(r0 + 2) * XS + k];
        float a3 = Xs[(r0 + 3) * XS + k];
        float4 wv = *(const float4*)(Ws + k * D + c0);
        acc[0][0] = fmaf(a0, wv.x, acc[0][0]);
        acc[0][1] = fmaf(a0, wv.y, acc[0][1]);
        acc[0][2] = fmaf(a0, wv.z, acc[0][2]);
        acc[0][3] = fmaf(a0, wv.w, acc[0][3]);
        acc[1][0] = fmaf(a1, wv.x, acc[1][0]);
        acc[1][1] = fmaf(a1, wv.y, acc[1][1]);
        acc[1][2] = fmaf(a1, wv.z, acc[1][2]);
        acc[1][3] = fmaf(a1, wv.w, acc[1][3]);
        acc[2][0] = fmaf(a2, wv.x, acc[2][0]);
        acc[2][1] = fmaf(a2, wv.y, acc[2][1]);
        acc[2][2] = fmaf(a2, wv.z, acc[2][2]);
        acc[2][3] = fmaf(a2, wv.w, acc[2][3]);
        acc[3][0] = fmaf(a3, wv.x, acc[3][0]);
        acc[3][1] = fmaf(a3, wv.y, acc[3][1]);
        acc[3][2] = fmaf(a3, wv.z, acc[3][2]);
        acc[3][3] = fmaf(a3, wv.w, acc[3][3]);
    }

    // Store 4x4 with dis[row] scaling folded in.
    #pragma unroll
    for (int i = 0; i < 4; i++) {
        int gr = row0 + r0 + i;
        if (gr < NN) {
            float dr = g_dis[gr];
            float4 o = make_float4(acc[i][0] * dr, acc[i][1] * dr,
                                   acc[i][2] * dr, acc[i][3] * dr);
            *(float4*)(g_buf1 + (size_t)gr * D + c0) = o;
        }
    }
}

// Pull aggregation: HALF-WARP per node (float4 lanes) -> 2 independent edge
// streams per warp (2x MLP).
//   g_buf2[n] = bias + dis[n] * ( h'[n] + sum_e h'[col[e]] )
// FUSED BN stats: per-feature sum/sumsq, halves combined via shfl, block
// reduce, one atomic per feature. Requires blockDim == 256, NN even.
__global__ void k_agg(const float* __restrict__ bias, int off) {
    __shared__ float ssum[8 * D], ssq[8 * D];
    int t = threadIdx.x;
    int warp = t >> 5, lane = t & 31;
    int half = lane >> 4, hl = lane & 15;     // half-warp id, lane within half
    int gwarp  = blockIdx.x * 8 + warp;
    int nwarps = gridDim.x * 8;
    const float4* __restrict__ H4 = (const float4*)g_buf1;
    float4 b = ((const float4*)bias)[hl];
    float4 ts = make_float4(0.f, 0.f, 0.f, 0.f);
    float4 tq = make_float4(0.f, 0.f, 0.f, 0.f);
    for (int pair = gwarp; pair < NN / 2; pair += nwarps) {
        int n = 2 * pair + half;
        float dn = g_dis[n];
        float4 acc = __ldg(&H4[(size_t)n * 16 + hl]);   // self term h'[n]
        int s0 = g_rowptr[n], e0 = g_rowptr[n + 1];
        #pragma unroll 4
        for (int i = s0; i < e0; i++) {
            int col = __ldg(&g_col[i]);                 // broadcast within half
            float4 v = __ldg(&H4[(size_t)col * 16 + hl]);
            acc.x += v.x; acc.y += v.y; acc.z += v.z; acc.w += v.w;
        }
        float4 o;
        o.x = fmaf(dn, acc.x, b.x);
        o.y = fmaf(dn, acc.y, b.y);
        o.z = fmaf(dn, acc.z, b.z);
        o.w = fmaf(dn, acc.w, b.w);
        ((float4*)g_buf2)[(size_t)n * 16 + hl] = o;
        ts.x += o.x; ts.y += o.y; ts.z += o.z; ts.w += o.w;
        tq.x = fmaf(o.x, o.x, tq.x);
        tq.y = fmaf(o.y, o.y, tq.y);
        tq.z = fmaf(o.z, o.z, tq.z);
        tq.w = fmaf(o.w, o.w, tq.w);
    }
    __syncwarp();
    // Combine the two halves (same features) with shuffles.
    ts.x += __shfl_down_sync(0xffffffffu, ts.x, 16);
    ts.y += __shfl_down_sync(0xffffffffu, ts.y, 16);
    ts.z += __shfl_down_sync(0xffffffffu, ts.z, 16);
    ts.w += __shfl_down_sync(0xffffffffu, ts.w, 16);
    tq.x += __shfl_down_sync(0xffffffffu, tq.x, 16);
    tq.y += __shfl_down_sync(0xffffffffu, tq.y, 16);
    tq.z += __shfl_down_sync(0xffffffffu, tq.z, 16);
    tq.w += __shfl_down_sync(0xffffffffu, tq.w, 16);
    if (half == 0) {
        ((float4*)(ssum + warp * D))[hl] = ts;
        ((float4*)(ssq  + warp * D))[hl] = tq;
    }
    __syncthreads();
    if (t < D) {
        float s = 0.0f, q = 0.0f;
        #pragma unroll
        for (int w = 0; w < 8; w++) {
            s += ssum[w * D + t];
            q += ssq [w * D + t];
        }
        atomicAdd(&g_bnsum[off + t],     s);
        atomicAdd(&g_bnsum[off + D + t], q);
    }
}

// Final BN+ReLU from g_buf2 (stats g_bnsum[128..255]) -> d_out. float4.
// Also resets g_deg for the NEXT call (no reader of g_deg in this kernel).
__global__ void k_apply(float4* __restrict__ out,
                        const float* __restrict__ gamma,
                        const float* __restrict__ beta) {
    __shared__ float s_sc[D], s_sh[D];
    int t = threadIdx.x;
    if (t < D) {
        float inv_n = 1.0f / (float)NN;
        float mu  = g_bnsum[128 + t] * inv_n;
        float var = g_bnsum[192 + t] * inv_n - mu * mu;
        float sc  = gamma[t] * rsqrtf(var + BN_EPS);
        s_sc[t] = sc;
        s_sh[t] = beta[t] - mu * sc;
    }
    __syncthreads();
    const float4* __restrict__ in = (const float4*)g_buf2;
    size_t total  = (size_t)NN * (D / 4);
    size_t stride = (size_t)gridDim.x * blockDim.x;
    for (size_t i = (size_t)blockIdx.x * blockDim.x + t; i < total; i += stride) {
        int f = ((int)i & 15) * 4;
        float4 v = in[i];
        v.x = fmaxf(fmaf(v.x, s_sc[f],     s_sh[f]),     0.0f);
        v.y = fmaxf(fmaf(v.y, s_sc[f + 1], s_sh[f + 1]), 0.0f);
        v.z = fmaxf(fmaf(v.z, s_sc[f + 2], s_sh[f + 2]), 0.0f);
        v.w = fmaxf(fmaf(v.w, s_sc[f + 3], s_sh[f + 3]), 0.0f);
        out[i] = v;
    }
    // Self-clean for next call.
    for (int i = blockIdx.x * blockDim.x + t; i < NN; i += (int)stride)
        g_deg[i] = 0;
}

// ---------------- launch ----------------
extern "C" void kernel_launch(void* const* d_in, const int* in_sizes, int n_in,
                              void* d_out, int out_size) {
    const float* x   = (const float*)d_in[0];
    const int*   ei  = (const int*)  d_in[1];
    const float* W1  = (const float*)d_in[2];
    const float* b1  = (const float*)d_in[3];
    const float* ga1 = (const float*)d_in[4];
    const float* be1 = (const float*)d_in[5];
    const float* W2  = (const float*)d_in[6];
    const float* b2  = (const float*)d_in[7];
    const float* ga2 = (const float*)d_in[8];
    const float* be2 = (const float*)d_in[9];
    float* out = (float*)d_out;

    const int4* src4 = (const int4*)ei;         // edge_index[0]
    const int4* dst4 = (const int4*)(ei + EE);  // edge_index[1]

    const int TB = 256;
    const int GEMM_BLKS = (NN + TM - 1) / TM;   // 1563
    const int WORK_BLKS = 1480;                 // grid-stride for agg

    // CSR build (k_count also resets psum/bnsum for this call)
    k_count  <<<2048, TB>>>(dst4);
    k_scan   <<<NCH, 1024>>>();
    k_scatter<<<2048, TB>>>(src4, dst4);

    // Layer 1
    k_gemm <<<GEMM_BLKS, TB>>>(x, W1, nullptr, nullptr, 0);   // buf1 = dis*(x@W1)
    k_agg  <<<WORK_BLKS, TB>>>(b1, 0);                        // buf2 = agg+b1, stats->[0:128)

    // Layer 2 (BN1+ReLU fused into GEMM staging)
    k_gemm <<<GEMM_BLKS, TB>>>(nullptr, W2, ga1, be1, 1);     // buf1 = dis*(relu(bn(buf2))@W2)
    k_agg  <<<WORK_BLKS, TB>>>(b2, 128);                      // buf2 = agg+b2, stats->[128:256)

    // Output (+ self-clean g_deg for next call)
    k_apply<<<2048, TB>>>((float4*)out, ga2, be2);
}